// round 15
// baseline (speedup 1.0000x reference)
#include <cuda_runtime.h>
#include <cuda_bf16.h>
#include <cuda_fp16.h>
#include <cstdint>

#define BQ 2
#define LQ 2048
#define EQ 1024
#define NLQ 2
#define DIQ 2048
#define DSQ 16
#define DCQ 4
#define DTRQ 64
#define TQ (BQ * LQ)   // 4096 tokens
#define NSEG 8
#define LSEG (LQ / NSEG)   // 256

// ---------------- scratch (device globals; no allocation allowed) ----------
__device__ float g_h[TQ * EQ];
__device__ __half g_xz16[TQ * 2 * DIQ];             // in_proj out, fp16
__device__ __half g_xc16[TQ * DIQ];                 // conv out fp16 (x_proj A + scan u)
__device__ __half g_xdbl16[TQ * 96];                // x_proj out fp16 (dt|B|C)
__device__ float g_xpart[8 * TQ * 128];
__device__ __half g_dt16[TQ * 128];                 // dt fp16 (padded to 128)
__device__ __half g_delta16[TQ * DIQ];              // softplus(dt_proj), fp16
__device__ float g_out[TQ * EQ];
__device__ float g_qseg[BQ * NSEG * DIQ * DSQ];     // segment-local final states
__device__ float g_dsum[BQ * NSEG * DIQ];           // per-segment sum of delta
__device__ __half g_a16[TQ * DIQ];                  // fp16 activations
__device__ __half g_w16i[NLQ * (2 * DIQ) * EQ];     // fp16 in_proj weights (all layers)
__device__ __half g_w16o[NLQ * EQ * DIQ];           // fp16 out_proj weights
__device__ __half g_w16x[NLQ * 128 * DIQ];          // fp16 x_proj weights (padded)
__device__ __half g_w16d[NLQ * DIQ * 128];          // fp16 dt_proj weights (K padded)

// ---------------- small helpers -------------------------------------------
__device__ __forceinline__ void cp_async4(void* smem, const void* gmem) {
    uint32_t s = (uint32_t)__cvta_generic_to_shared(smem);
    asm volatile("cp.async.ca.shared.global [%0], [%1], 4;\n" :: "r"(s), "l"(gmem));
}
__device__ __forceinline__ void cp_async16(uint32_t s, const void* gmem) {
    asm volatile("cp.async.cg.shared.global [%0], [%1], 16;\n" :: "r"(s), "l"(gmem));
}
__device__ __forceinline__ void cp_commit() { asm volatile("cp.async.commit_group;\n"); }
__device__ __forceinline__ void cp_wait1()  { asm volatile("cp.async.wait_group 1;\n"); }

// ---------------- embed: h = x + pos (+ fp16 cast for in_proj A) ------------
__global__ void embed_kernel(const float* __restrict__ x,
                             const float* __restrict__ pos,
                             float* __restrict__ h,
                             __half* __restrict__ a16) {
    int idx = blockIdx.x * blockDim.x + threadIdx.x;
    if (idx >= TQ * EQ) return;
    int e = idx % EQ;
    int l = (idx / EQ) % LQ;
    float v = x[idx] + pos[l * EQ + e];
    h[idx] = v;
    a16[idx] = __float2half(v);
}

// ---------------- all-layer weight prep (one launch, before the loop) -------
#define NI (2 * DIQ * EQ)
#define NO (EQ * DIQ)
#define NX (128 * DIQ)
#define ND (DIQ * 128)
#define NPER (NI + NO + NX + ND)
__global__ void prep_all_kernel(const float* __restrict__ inw,
                                const float* __restrict__ ow,
                                const float* __restrict__ xw,
                                const float* __restrict__ dtw,
                                __half* __restrict__ w16i,
                                __half* __restrict__ w16o,
                                __half* __restrict__ w16x,
                                __half* __restrict__ w16d) {
    int idx = blockIdx.x * blockDim.x + threadIdx.x;
    if (idx >= NLQ * NPER) return;
    int layer = idx / NPER;
    int i = idx % NPER;
    if (i < NI) {
        w16i[(size_t)layer * NI + i] =
            __float2half(inw[(size_t)layer * NI + i]);
    } else if (i < NI + NO) {
        int j = i - NI;
        w16o[(size_t)layer * NO + j] =
            __float2half(ow[(size_t)layer * NO + j]);
    } else if (i < NI + NO + NX) {
        int j = i - NI - NO;
        int r = j / DIQ, k = j % DIQ;
        float v = (r < 96) ? xw[(size_t)layer * 96 * DIQ + (size_t)r * DIQ + k] : 0.f;
        w16x[(size_t)layer * NX + j] = __float2half(v);
    } else {
        int j = i - NI - NO - NX;
        int r = j / 128, k = j % 128;
        float v = (k < DTRQ) ? dtw[(size_t)layer * DIQ * DTRQ + (size_t)r * DTRQ + k] : 0.f;
        w16d[(size_t)layer * ND + j] = __float2half(v);
    }
}

// ---------------- mma.sync fp16 NT GEMM: C[M,N]=A[M,K]*W[N,K]^T -------------
// Template BN: 128 (occ 2) or 256 (occ 1, 64x64 warp tile). Dynamic smem.
// block tile 128xBN, K-chunk 32, 4-stage cp.async pipeline; 8 warps 2x4.
// split-K via blockIdx.z. epi=1: softplus(v+bias). Ch non-null: fp16 out.
#define MST 4

__device__ __forceinline__ uint32_t swz64(int row, int kb) {
    return (uint32_t)(row * 64 + ((kb ^ ((row >> 1) & 3)) << 4));
}

template <int BN>
__global__ __launch_bounds__(256, (BN == 128) ? 2 : 1)
void mma_gemm_kernel(const void* __restrict__ Av, const void* __restrict__ Wv,
                     float* __restrict__ C, __half* __restrict__ Ch,
                     int K, int ldc,
                     const float* __restrict__ bias, int epi) {
    constexpr int STB = (128 + BN) * 64;   // stage bytes
    constexpr int WN = BN / 4;             // warp n-extent
    constexpr int NT = WN / 8;             // mma n-tiles per warp
    extern __shared__ __align__(128) char smem[];
    const uint32_t sbase = (uint32_t)__cvta_generic_to_shared(smem);

    const int tid = threadIdx.x;
    const int lane = tid & 31;
    const int warp = tid >> 5;
    const int wm = warp >> 2;
    const int wn = warp & 3;
    const int bm = blockIdx.y * 128;
    const int bn = blockIdx.x * BN;
    const int NC_total = K >> 5;
    const int kch = NC_total / gridDim.z;
    const int c0 = blockIdx.z * kch;
    const int c1 = c0 + kch;
    if (gridDim.z > 1) C += (size_t)blockIdx.z * (gridDim.y * 128) * ldc;

    const char* Ab = (const char*)Av;
    const char* Wb = (const char*)Wv;
    const size_t pitch = (size_t)K * 2;

    const int frow = tid >> 2;
    const int fkb = tid & 3;

    auto fill = [&](int c, int s) {
        uint32_t sa = sbase + s * STB;
        uint32_t sb = sa + 128 * 64;
        size_t gofs = (size_t)c * 64 + (size_t)fkb * 16;
#pragma unroll
        for (int p = 0; p < 2; p++) {
            int row = frow + 64 * p;
            cp_async16(sa + swz64(row, fkb), Ab + (size_t)(bm + row) * pitch + gofs);
        }
#pragma unroll
        for (int p = 0; p < BN / 64; p++) {
            int row = frow + 64 * p;
            cp_async16(sb + swz64(row, fkb), Wb + (size_t)(bn + row) * pitch + gofs);
        }
        cp_commit();
    };

    uint32_t a_off[4][2];
    {
        int mtx = lane >> 3;
        int arow = wm * 64 + (mtx & 1) * 8 + (lane & 7);
        int akb = mtx >> 1;
#pragma unroll
        for (int mi = 0; mi < 4; mi++)
#pragma unroll
            for (int ks = 0; ks < 2; ks++)
                a_off[mi][ks] = swz64(arow + mi * 16, akb + ks * 2);
    }
    uint32_t b_off[NT / 2][2];
    {
        int mtx = lane >> 3;
        int bkb = mtx & 1;
#pragma unroll
        for (int nh = 0; nh < NT / 2; nh++) {
            int brow = wn * WN + nh * 16 + (mtx >> 1) * 8 + (lane & 7);
#pragma unroll
            for (int ks = 0; ks < 2; ks++)
                b_off[nh][ks] = swz64(brow, bkb + ks * 2);
        }
    }

    float acc[4][NT][4];
#pragma unroll
    for (int i = 0; i < 4; i++)
#pragma unroll
        for (int j = 0; j < NT; j++)
#pragma unroll
            for (int q = 0; q < 4; q++) acc[i][j][q] = 0.f;

    fill(c0, 0);
    if (c0 + 1 < c1) fill(c0 + 1, 1);
    if (c0 + 2 < c1) fill(c0 + 2, 2);

    for (int c = c0; c < c1; c++) {
        int s = (c - c0) % MST;
        asm volatile("cp.async.wait_group %0;" :: "n"(MST - 2));
        __syncthreads();
        uint32_t sa = sbase + s * STB;
        uint32_t sb = sa + 128 * 64;
#pragma unroll
        for (int ks = 0; ks < 2; ks++) {
            uint32_t a[4][4];
#pragma unroll
            for (int mi = 0; mi < 4; mi++)
                asm volatile("ldmatrix.sync.aligned.m8n8.x4.shared.b16 {%0,%1,%2,%3}, [%4];"
                             : "=r"(a[mi][0]), "=r"(a[mi][1]), "=r"(a[mi][2]), "=r"(a[mi][3])
                             : "r"(sa + a_off[mi][ks]));
            uint32_t b[NT][2];
#pragma unroll
            for (int nh = 0; nh < NT / 2; nh++) {
                uint32_t r0, r1, r2, r3;
                asm volatile("ldmatrix.sync.aligned.m8n8.x4.shared.b16 {%0,%1,%2,%3}, [%4];"
                             : "=r"(r0), "=r"(r1), "=r"(r2), "=r"(r3)
                             : "r"(sb + b_off[nh][ks]));
                b[2 * nh][0] = r0; b[2 * nh][1] = r1;
                b[2 * nh + 1][0] = r2; b[2 * nh + 1][1] = r3;
            }
#pragma unroll
            for (int mi = 0; mi < 4; mi++)
#pragma unroll
                for (int ni = 0; ni < NT; ni++)
                    asm volatile(
                        "mma.sync.aligned.m16n8k16.row.col.f32.f16.f16.f32 "
                        "{%0,%1,%2,%3}, {%4,%5,%6,%7}, {%8,%9}, {%0,%1,%2,%3};"
                        : "+f"(acc[mi][ni][0]), "+f"(acc[mi][ni][1]),
                          "+f"(acc[mi][ni][2]), "+f"(acc[mi][ni][3])
                        : "r"(a[mi][0]), "r"(a[mi][1]), "r"(a[mi][2]), "r"(a[mi][3]),
                          "r"(b[ni][0]), "r"(b[ni][1]));
        }
        if (c + 3 < c1) fill(c + 3, (c + 3 - c0) % MST);
        else cp_commit();
    }

    int r0 = bm + wm * 64 + (lane >> 2);
    int col0 = bn + wn * WN + 2 * (lane & 3);
#pragma unroll
    for (int mi = 0; mi < 4; mi++)
#pragma unroll
        for (int ni = 0; ni < NT; ni++) {
            int cc = col0 + ni * 8;
            float v0 = acc[mi][ni][0], v1 = acc[mi][ni][1];
            float v2 = acc[mi][ni][2], v3 = acc[mi][ni][3];
            if (epi == 1) {
                float b0 = bias[cc], b1 = bias[cc + 1];
                v0 += b0; v1 += b1; v2 += b0; v3 += b1;
                v0 = (v0 > 20.f) ? v0 : log1pf(__expf(v0));
                v1 = (v1 > 20.f) ? v1 : log1pf(__expf(v1));
                v2 = (v2 > 20.f) ? v2 : log1pf(__expf(v2));
                v3 = (v3 > 20.f) ? v3 : log1pf(__expf(v3));
            }
            if (Ch) {
                *(__half2*)(Ch + (size_t)(r0 + mi * 16) * ldc + cc) =
                    __floats2half2_rn(v0, v1);
                *(__half2*)(Ch + (size_t)(r0 + mi * 16 + 8) * ldc + cc) =
                    __floats2half2_rn(v2, v3);
            } else {
                float* p0 = C + (size_t)(r0 + mi * 16) * ldc + cc;
                float* p1 = p0 + 8 * ldc;
                *(float2*)p0 = make_float2(v0, v1);
                *(float2*)p1 = make_float2(v2, v3);
            }
        }
}

// ---------------- reduce x_proj partials; emit xdbl fp16 + dt fp16 ----------
__global__ void reduce8x_kernel(const float* __restrict__ part,
                                __half* __restrict__ xdbl,
                                __half* __restrict__ dt16) {
    int i = blockIdx.x * blockDim.x + threadIdx.x;
    if (i >= TQ * 128) return;
    int t = i >> 7, c = i & 127;
    float s = 0.f;
#pragma unroll
    for (int p = 0; p < 8; p++) s += part[(size_t)p * TQ * 128 + i];
    if (c < 96) xdbl[t * 96 + c] = __float2half(s);
    dt16[i] = __float2half((c < DTRQ) ? s : 0.f);
}

// ---------------- causal depthwise conv (DC=4) + silu -> fp16 ---------------
__global__ void conv_silu_kernel(const __half* __restrict__ xz,
                                 const float* __restrict__ cw,
                                 const float* __restrict__ cb,
                                 __half* __restrict__ xc16) {
    int idx = blockIdx.x * blockDim.x + threadIdx.x;
    if (idx >= TQ * DIQ) return;
    int d = idx % DIQ;
    int t = idx / DIQ;
    int b = t / LQ;
    int l = t % LQ;
    float acc = cb[d];
#pragma unroll
    for (int k = 0; k < DCQ; k++) {
        int ll = l + k - (DCQ - 1);
        if (ll >= 0)
            acc = fmaf(cw[d * DCQ + k],
                       __half2float(xz[(size_t)(b * LQ + ll) * (2 * DIQ) + d]), acc);
    }
    float sig = 1.f / (1.f + __expf(-acc));
    xc16[idx] = __float2half(acc * sig);
}

// ================== chunked parallel scan =================================
#define SLC 64

// ---- pass 1: segment-local scan from 0 -> q[d,n]; also sum(delta) ----------
__global__ __launch_bounds__(256, 8)
void scan_p1_kernel(const __half* __restrict__ delta, const __half* __restrict__ u,
                    const __half* __restrict__ xdbl, const float* __restrict__ A_log,
                    float* __restrict__ qseg, float* __restrict__ dsum) {
    __shared__ __half s_d[2][SLC * 16];
    __shared__ __half s_u[2][SLC * 16];
    __shared__ __half s_B[2][SLC * 16];

    int d0 = blockIdx.x * 16;
    int seg = blockIdx.y;
    int b = blockIdx.z;
    int tid = threadIdx.x;
    int warp = tid >> 5;
    int lane = tid & 31;
    int chl = warp * 2 + (lane >> 4);
    int d = d0 + chl;
    int n = lane & 15;

    float Aval = -__expf(A_log[d * DSQ + n]);
    float hst = 0.f;
    float ds = 0.f;

    const int NCC = LSEG / SLC;   // 4
    int lbase = seg * LSEG;

    auto load_chunk = [&](int c, int buf) {
        int l0 = lbase + c * SLC;
#pragma unroll
        for (int e2 = tid; e2 < SLC * 8; e2 += 256) {
            int l = e2 >> 3, cp2 = e2 & 7;
            size_t t = (size_t)(b * LQ + l0 + l);
            cp_async4(&s_d[buf][l * 16 + cp2 * 2], delta + t * DIQ + d0 + cp2 * 2);
            cp_async4(&s_u[buf][l * 16 + cp2 * 2], u + t * DIQ + d0 + cp2 * 2);
            cp_async4(&s_B[buf][l * 16 + cp2 * 2], xdbl + t * 96 + DTRQ + cp2 * 2);
        }
        cp_commit();
    };

    load_chunk(0, 0);
    for (int c = 0; c < NCC; c++) {
        int buf = c & 1;
        if (c + 1 < NCC) load_chunk(c + 1, (c + 1) & 1);
        else cp_commit();
        cp_wait1();
        __syncthreads();
#pragma unroll 8
        for (int l = 0; l < SLC; l++) {
            float dl = __half2float(s_d[buf][l * 16 + chl]);
            float uu = __half2float(s_u[buf][l * 16 + chl]);
            float Bv = __half2float(s_B[buf][l * 16 + n]);
            float a = __expf(dl * Aval);
            hst = fmaf(a, hst, dl * uu * Bv);
            ds += dl;
        }
        __syncthreads();
    }
    size_t base = ((size_t)(b * NSEG + seg) * DIQ + d);
    qseg[base * DSQ + n] = hst;
    if (n == 0) dsum[base] = ds;
}

// ---- pass 3: per-block prefix from qseg/dsum, then segment scan, emit y ----
__global__ __launch_bounds__(256, 4)
void scan_p3_kernel(const __half* __restrict__ delta, const __half* __restrict__ u,
                    const __half* __restrict__ xdbl, const __half* __restrict__ xz,
                    const float* __restrict__ A_log, const float* __restrict__ Dskip,
                    const float* __restrict__ qseg, const float* __restrict__ dsum,
                    __half* __restrict__ a16) {
    __shared__ __half s_d[2][SLC * 16];
    __shared__ __half s_u[2][SLC * 16];
    __shared__ __half s_z[2][SLC * 16];
    __shared__ __half s_B[2][SLC * 16];
    __shared__ __half s_C[2][SLC * 16];
    __shared__ __half s_y[SLC * 16];

    int d0 = blockIdx.x * 16;
    int seg = blockIdx.y;
    int b = blockIdx.z;
    int tid = threadIdx.x;
    int warp = tid >> 5;
    int lane = tid & 31;
    int chl = warp * 2 + (lane >> 4);
    int d = d0 + chl;
    int n = lane & 15;

    float Aval = -__expf(A_log[d * DSQ + n]);
    float Dval = Dskip[d];

    // in-register prefix over earlier segments (combine fused in)
    float hst = 0.f;
    for (int s = 0; s < seg; s++) {
        size_t base = ((size_t)(b * NSEG + s) * DIQ + d);
        hst = __expf(Aval * dsum[base]) * hst + qseg[base * DSQ + n];
    }

    const int NCC = LSEG / SLC;
    int lbase = seg * LSEG;

    auto load_chunk = [&](int c, int buf) {
        int l0 = lbase + c * SLC;
#pragma unroll
        for (int e2 = tid; e2 < SLC * 8; e2 += 256) {
            int l = e2 >> 3, cp2 = e2 & 7;
            size_t t = (size_t)(b * LQ + l0 + l);
            cp_async4(&s_d[buf][l * 16 + cp2 * 2], delta + t * DIQ + d0 + cp2 * 2);
            cp_async4(&s_u[buf][l * 16 + cp2 * 2], u + t * DIQ + d0 + cp2 * 2);
            cp_async4(&s_z[buf][l * 16 + cp2 * 2],
                      xz + t * (2 * DIQ) + DIQ + d0 + cp2 * 2);
            cp_async4(&s_B[buf][l * 16 + cp2 * 2], xdbl + t * 96 + DTRQ + cp2 * 2);
            cp_async4(&s_C[buf][l * 16 + cp2 * 2],
                      xdbl + t * 96 + DTRQ + DSQ + cp2 * 2);
        }
        cp_commit();
    };

    load_chunk(0, 0);
    for (int c = 0; c < NCC; c++) {
        int buf = c & 1;
        if (c + 1 < NCC) load_chunk(c + 1, (c + 1) & 1);
        else cp_commit();
        cp_wait1();
        __syncthreads();
#pragma unroll 4
        for (int l = 0; l < SLC; l++) {
            float dl = __half2float(s_d[buf][l * 16 + chl]);
            float uu = __half2float(s_u[buf][l * 16 + chl]);
            float Bv = __half2float(s_B[buf][l * 16 + n]);
            float Cv = __half2float(s_C[buf][l * 16 + n]);
            float a = __expf(dl * Aval);
            hst = fmaf(a, hst, dl * uu * Bv);
            float p = hst * Cv;
            p += __shfl_xor_sync(0xffffffffu, p, 8);
            p += __shfl_xor_sync(0xffffffffu, p, 4);
            p += __shfl_xor_sync(0xffffffffu, p, 2);
            p += __shfl_xor_sync(0xffffffffu, p, 1);
            if (n == 0) {
                float zz = __half2float(s_z[buf][l * 16 + chl]);
                float sig = 1.f / (1.f + __expf(-zz));
                s_y[l * 16 + chl] = __float2half((p + uu * Dval) * zz * sig);
            }
        }
        __syncthreads();
        int l0 = lbase + c * SLC;
#pragma unroll
        for (int e = tid; e < SLC * 16; e += 256) {
            int l = e >> 4, ch = e & 15;
            a16[(size_t)(b * LQ + l0 + l) * DIQ + d0 + ch] = s_y[e];
        }
        __syncthreads();
    }
}

// ---------------- residual add + rmsnorm (+ optional fp16 cast) -------------
__global__ void add_rmsnorm_kernel(const float* __restrict__ yo,
                                   const float* __restrict__ hin,
                                   const float* __restrict__ w,
                                   float* __restrict__ out,
                                   __half* __restrict__ a16) {
    int row = blockIdx.x;
    const float* yr = yo + (size_t)row * EQ;
    const float* hr = hin + (size_t)row * EQ;
    int tid = threadIdx.x;
    float v[4];
    float ss = 0.f;
#pragma unroll
    for (int i = 0; i < 4; i++) {
        int j = tid + 256 * i;
        v[i] = yr[j] + hr[j];
        ss = fmaf(v[i], v[i], ss);
    }
#pragma unroll
    for (int off = 16; off; off >>= 1) ss += __shfl_xor_sync(0xffffffffu, ss, off);
    __shared__ float sp[8];
    if ((tid & 31) == 0) sp[tid >> 5] = ss;
    __syncthreads();
    if (tid == 0) {
        float t = 0.f;
#pragma unroll
        for (int i = 0; i < 8; i++) t += sp[i];
        sp[0] = t;
    }
    __syncthreads();
    float scale = rsqrtf(sp[0] * (1.f / EQ) + 1e-6f);
#pragma unroll
    for (int i = 0; i < 4; i++) {
        int j = tid + 256 * i;
        float ov = v[i] * scale * w[j];
        out[(size_t)row * EQ + j] = ov;
        if (a16) a16[(size_t)row * EQ + j] = __float2half(ov);
    }
}

// ---------------- host launcher ---------------------------------------------
extern "C" void kernel_launch(void* const* d_in, const int* in_sizes, int n_in,
                              void* d_out, int out_size) {
    const float* x    = (const float*)d_in[0];
    const float* pos  = (const float*)d_in[1];
    const float* inw  = (const float*)d_in[2];
    const float* cw   = (const float*)d_in[3];
    const float* cb   = (const float*)d_in[4];
    const float* xw   = (const float*)d_in[5];
    const float* dtw  = (const float*)d_in[6];
    const float* dtb  = (const float*)d_in[7];
    const float* alog = (const float*)d_in[8];
    const float* dsk  = (const float*)d_in[9];
    const float* ow   = (const float*)d_in[10];
    const float* nw   = (const float*)d_in[11];
    float* out = (float*)d_out;

    float *ph, *pxpart, *pout, *pq, *pds;
    __half *pxz16, *pxc16, *pxdbl16, *pdt16, *pdelta16, *pa16;
    __half *pw16i, *pw16o, *pw16x, *pw16d;
    cudaGetSymbolAddress((void**)&ph, g_h);
    cudaGetSymbolAddress((void**)&pxz16, g_xz16);
    cudaGetSymbolAddress((void**)&pxc16, g_xc16);
    cudaGetSymbolAddress((void**)&pxdbl16, g_xdbl16);
    cudaGetSymbolAddress((void**)&pxpart, g_xpart);
    cudaGetSymbolAddress((void**)&pdt16, g_dt16);
    cudaGetSymbolAddress((void**)&pdelta16, g_delta16);
    cudaGetSymbolAddress((void**)&pout, g_out);
    cudaGetSymbolAddress((void**)&pq, g_qseg);
    cudaGetSymbolAddress((void**)&pds, g_dsum);
    cudaGetSymbolAddress((void**)&pa16, g_a16);
    cudaGetSymbolAddress((void**)&pw16i, g_w16i);
    cudaGetSymbolAddress((void**)&pw16o, g_w16o);
    cudaGetSymbolAddress((void**)&pw16x, g_w16x);
    cudaGetSymbolAddress((void**)&pw16d, g_w16d);

    const int SM128 = MST * (128 + 128) * 64;   // 65536
    const int SM256 = MST * (128 + 256) * 64;   // 98304
    cudaFuncSetAttribute(mma_gemm_kernel<128>,
                         cudaFuncAttributeMaxDynamicSharedMemorySize, SM128);
    cudaFuncSetAttribute(mma_gemm_kernel<256>,
                         cudaFuncAttributeMaxDynamicSharedMemorySize, SM256);

    // all-layer weight prep (single launch, off the per-layer critical path)
    prep_all_kernel<<<(NLQ * NPER + 255) / 256, 256>>>(
        inw, ow, xw, dtw, pw16i, pw16o, pw16x, pw16d);

    // h = x + pos, and fp16 cast for layer-0 in_proj
    embed_kernel<<<(TQ * EQ + 255) / 256, 256>>>(x, pos, ph, pa16);

    for (int layer = 0; layer < NLQ; layer++) {
        const float* cw_l  = cw  + (size_t)layer * DIQ * DCQ;
        const float* cb_l  = cb  + (size_t)layer * DIQ;
        const float* dtb_l = dtb + (size_t)layer * DIQ;
        const float* al_l  = alog + (size_t)layer * DIQ * DSQ;
        const float* ds_l  = dsk + (size_t)layer * DIQ;
        const float* nw_l  = nw  + (size_t)layer * EQ;
        const __half* w16i_l = pw16i + (size_t)layer * NI;
        const __half* w16o_l = pw16o + (size_t)layer * NO;
        const __half* w16x_l = pw16x + (size_t)layer * NX;
        const __half* w16d_l = pw16d + (size_t)layer * ND;

        // in_proj: xz = h @ in_w^T  (fp16, K=1024, 128x256 tile, fp16 out)
        mma_gemm_kernel<256><<<dim3(2 * DIQ / 256, TQ / 128, 1), 256, SM256>>>(
            pa16, w16i_l, nullptr, pxz16, EQ, 2 * DIQ, nullptr, 0);

        // xc = silu(causal_conv(xz[:, :DI]) + cb)  (fp16 only)
        conv_silu_kernel<<<(TQ * DIQ + 255) / 256, 256>>>(pxz16, cw_l, cb_l, pxc16);

        // x_proj: x_dbl = xc @ xw^T  (fp16, pad N 96->128, split-K=8)
        mma_gemm_kernel<128><<<dim3(1, TQ / 128, 8), 256, SM128>>>(
            pxc16, w16x_l, pxpart, nullptr, DIQ, 128, nullptr, 0);
        reduce8x_kernel<<<(TQ * 128 + 255) / 256, 256>>>(pxpart, pxdbl16, pdt16);

        // dt_proj: delta = softplus(dt @ dtw^T + dtb)  (128x256 tile)
        mma_gemm_kernel<256><<<dim3(DIQ / 256, TQ / 128, 1), 256, SM256>>>(
            pdt16, w16d_l, nullptr, pdelta16, 128, DIQ, dtb_l, 1);

        // chunked selective scan: pass1 -> pass3 (p3 does its own prefix)
        scan_p1_kernel<<<dim3(DIQ / 16, NSEG, BQ), 256>>>(
            pdelta16, pxc16, pxdbl16, al_l, pq, pds);
        scan_p3_kernel<<<dim3(DIQ / 16, NSEG, BQ), 256>>>(
            pdelta16, pxc16, pxdbl16, pxz16, al_l, ds_l, pq, pds, pa16);

        // out_proj: out = y @ ow^T  (128x256 tile, single wave)
        mma_gemm_kernel<256><<<dim3(EQ / 256, TQ / 128, 1), 256, SM256>>>(
            pa16, w16o_l, pout, nullptr, DIQ, EQ, nullptr, 0);

        // h = rmsnorm(out + h) * norm_w  (+ fp16 cast for next layer's in_proj)
        float* dst = (layer == NLQ - 1) ? out : ph;
        __half* nxt = (layer == NLQ - 1) ? (__half*)nullptr : pa16;
        add_rmsnorm_kernel<<<TQ, 256>>>(pout, ph, nw_l, dst, nxt);
    }
}

// round 16
// speedup vs baseline: 1.1146x; 1.1146x over previous
#include <cuda_runtime.h>
#include <cuda_bf16.h>
#include <cuda_fp16.h>
#include <cstdint>

#define BQ 2
#define LQ 2048
#define EQ 1024
#define NLQ 2
#define DIQ 2048
#define DSQ 16
#define DCQ 4
#define DTRQ 64
#define TQ (BQ * LQ)   // 4096 tokens
#define NSEG 8
#define LSEG (LQ / NSEG)   // 256

// ---------------- scratch (device globals; no allocation allowed) ----------
__device__ float g_h[TQ * EQ];
__device__ __half g_xz16[TQ * 2 * DIQ];             // in_proj out, fp16
__device__ __half g_xc16[TQ * DIQ];                 // conv out fp16 (x_proj A + scan u)
__device__ float g_xdbl[TQ * 96];                   // x_proj out fp32 (dt|B|C)
__device__ float g_xpart[8 * TQ * 128];
__device__ __half g_dt16[TQ * 128];                 // dt fp16 (padded to 128)
__device__ __half g_delta16[TQ * DIQ];              // softplus(dt_proj), fp16
__device__ float g_out[TQ * EQ];
__device__ float g_qseg[BQ * NSEG * DIQ * DSQ];     // segment-local final states
__device__ float g_dsum[BQ * NSEG * DIQ];           // per-segment sum of delta
__device__ __half g_a16[TQ * DIQ];                  // fp16 activations
__device__ __half g_w16i[NLQ * (2 * DIQ) * EQ];     // fp16 in_proj weights (all layers)
__device__ __half g_w16o[NLQ * EQ * DIQ];           // fp16 out_proj weights
__device__ __half g_w16x[NLQ * 128 * DIQ];          // fp16 x_proj weights (padded)
__device__ __half g_w16d[NLQ * DIQ * 128];          // fp16 dt_proj weights (K padded)

// ---------------- small helpers -------------------------------------------
__device__ __forceinline__ void cp_async4(void* smem, const void* gmem) {
    uint32_t s = (uint32_t)__cvta_generic_to_shared(smem);
    asm volatile("cp.async.ca.shared.global [%0], [%1], 4;\n" :: "r"(s), "l"(gmem));
}
__device__ __forceinline__ void cp_async16(uint32_t s, const void* gmem) {
    asm volatile("cp.async.cg.shared.global [%0], [%1], 16;\n" :: "r"(s), "l"(gmem));
}
__device__ __forceinline__ void cp_commit() { asm volatile("cp.async.commit_group;\n"); }
__device__ __forceinline__ void cp_wait1()  { asm volatile("cp.async.wait_group 1;\n"); }

// ---------------- embed: h = x + pos (+ fp16 cast for in_proj A) ------------
__global__ void embed_kernel(const float* __restrict__ x,
                             const float* __restrict__ pos,
                             float* __restrict__ h,
                             __half* __restrict__ a16) {
    int idx = blockIdx.x * blockDim.x + threadIdx.x;
    if (idx >= TQ * EQ) return;
    int e = idx % EQ;
    int l = (idx / EQ) % LQ;
    float v = x[idx] + pos[l * EQ + e];
    h[idx] = v;
    a16[idx] = __float2half(v);
}

// ---------------- all-layer weight prep (one launch, before the loop) -------
#define NI (2 * DIQ * EQ)
#define NO (EQ * DIQ)
#define NX (128 * DIQ)
#define ND (DIQ * 128)
#define NPER (NI + NO + NX + ND)
__global__ void prep_all_kernel(const float* __restrict__ inw,
                                const float* __restrict__ ow,
                                const float* __restrict__ xw,
                                const float* __restrict__ dtw,
                                __half* __restrict__ w16i,
                                __half* __restrict__ w16o,
                                __half* __restrict__ w16x,
                                __half* __restrict__ w16d) {
    int idx = blockIdx.x * blockDim.x + threadIdx.x;
    if (idx >= NLQ * NPER) return;
    int layer = idx / NPER;
    int i = idx % NPER;
    if (i < NI) {
        w16i[(size_t)layer * NI + i] =
            __float2half(inw[(size_t)layer * NI + i]);
    } else if (i < NI + NO) {
        int j = i - NI;
        w16o[(size_t)layer * NO + j] =
            __float2half(ow[(size_t)layer * NO + j]);
    } else if (i < NI + NO + NX) {
        int j = i - NI - NO;
        int r = j / DIQ, k = j % DIQ;
        float v = (r < 96) ? xw[(size_t)layer * 96 * DIQ + (size_t)r * DIQ + k] : 0.f;
        w16x[(size_t)layer * NX + j] = __float2half(v);
    } else {
        int j = i - NI - NO - NX;
        int r = j / 128, k = j % 128;
        float v = (k < DTRQ) ? dtw[(size_t)layer * DIQ * DTRQ + (size_t)r * DTRQ + k] : 0.f;
        w16d[(size_t)layer * ND + j] = __float2half(v);
    }
}

// ---------------- mma.sync fp16 NT GEMM: C[M,N]=A[M,K]*W[N,K]^T -------------
// block tile 128x128, K-chunk 64 (128B rows, SW128 swizzle), 3-stage pipeline,
// occ 2, 8 warps 2x4 (warp tile 64x32). split-K via blockIdx.z.
// epi=1: softplus(v+bias). Ch non-null: fp16 out.
#define MST 3
#define STB (256 * 128)          // stage bytes: 256 rows x 128B

__device__ __forceinline__ uint32_t swz128(int row, int c16) {
    return (uint32_t)(row * 128 + ((c16 ^ (row & 7)) << 4));
}

__global__ __launch_bounds__(256, 2)
void mma_gemm_kernel(const void* __restrict__ Av, const void* __restrict__ Wv,
                     float* __restrict__ C, __half* __restrict__ Ch,
                     int K, int ldc,
                     const float* __restrict__ bias, int epi) {
    extern __shared__ __align__(128) char smem[];
    const uint32_t sbase = (uint32_t)__cvta_generic_to_shared(smem);

    const int tid = threadIdx.x;
    const int lane = tid & 31;
    const int warp = tid >> 5;
    const int wm = warp >> 2;
    const int wn = warp & 3;
    const int bm = blockIdx.y * 128;
    const int bn = blockIdx.x * 128;
    const int NC_total = K >> 6;           // chunks of 64
    const int kch = NC_total / gridDim.z;
    const int c0 = blockIdx.z * kch;
    const int c1 = c0 + kch;
    if (gridDim.z > 1) C += (size_t)blockIdx.z * (gridDim.y * 128) * ldc;

    const char* Ab = (const char*)Av;
    const char* Wb = (const char*)Wv;
    const size_t pitch = (size_t)K * 2;

    const int frow = tid >> 3;             // 0..31
    const int fkb = tid & 7;               // 16B column 0..7

    auto fill = [&](int c, int s) {
        uint32_t sa = sbase + s * STB;
        uint32_t sb = sa + 128 * 128;
        size_t gofs = (size_t)c * 128 + (size_t)fkb * 16;
#pragma unroll
        for (int p = 0; p < 4; p++) {
            int row = frow + 32 * p;
            cp_async16(sa + swz128(row, fkb), Ab + (size_t)(bm + row) * pitch + gofs);
            cp_async16(sb + swz128(row, fkb), Wb + (size_t)(bn + row) * pitch + gofs);
        }
        cp_commit();
    };

    uint32_t a_off[4][4];
    {
        int mtx = lane >> 3;
        int arow = wm * 64 + (mtx & 1) * 8 + (lane & 7);
        int akb = mtx >> 1;
#pragma unroll
        for (int mi = 0; mi < 4; mi++)
#pragma unroll
            for (int ks = 0; ks < 4; ks++)
                a_off[mi][ks] = swz128(arow + mi * 16, akb + ks * 2);
    }
    uint32_t b_off[2][4];
    {
        int mtx = lane >> 3;
        int bkb = mtx & 1;
#pragma unroll
        for (int nh = 0; nh < 2; nh++) {
            int brow = wn * 32 + nh * 16 + (mtx >> 1) * 8 + (lane & 7);
#pragma unroll
            for (int ks = 0; ks < 4; ks++)
                b_off[nh][ks] = swz128(brow, bkb + ks * 2);
        }
    }

    float acc[4][4][4];
#pragma unroll
    for (int i = 0; i < 4; i++)
#pragma unroll
        for (int j = 0; j < 4; j++)
#pragma unroll
            for (int q = 0; q < 4; q++) acc[i][j][q] = 0.f;

    fill(c0, 0);
    if (c0 + 1 < c1) fill(c0 + 1, 1);

    for (int c = c0; c < c1; c++) {
        int s = (c - c0) % MST;
        asm volatile("cp.async.wait_group %0;" :: "n"(MST - 2));
        __syncthreads();
        uint32_t sa = sbase + s * STB;
        uint32_t sb = sa + 128 * 128;
#pragma unroll
        for (int ks = 0; ks < 4; ks++) {
            uint32_t a[4][4];
#pragma unroll
            for (int mi = 0; mi < 4; mi++)
                asm volatile("ldmatrix.sync.aligned.m8n8.x4.shared.b16 {%0,%1,%2,%3}, [%4];"
                             : "=r"(a[mi][0]), "=r"(a[mi][1]), "=r"(a[mi][2]), "=r"(a[mi][3])
                             : "r"(sa + a_off[mi][ks]));
            uint32_t b[4][2];
#pragma unroll
            for (int nh = 0; nh < 2; nh++) {
                uint32_t r0, r1, r2, r3;
                asm volatile("ldmatrix.sync.aligned.m8n8.x4.shared.b16 {%0,%1,%2,%3}, [%4];"
                             : "=r"(r0), "=r"(r1), "=r"(r2), "=r"(r3)
                             : "r"(sb + b_off[nh][ks]));
                b[2 * nh][0] = r0; b[2 * nh][1] = r1;
                b[2 * nh + 1][0] = r2; b[2 * nh + 1][1] = r3;
            }
#pragma unroll
            for (int mi = 0; mi < 4; mi++)
#pragma unroll
                for (int ni = 0; ni < 4; ni++)
                    asm volatile(
                        "mma.sync.aligned.m16n8k16.row.col.f32.f16.f16.f32 "
                        "{%0,%1,%2,%3}, {%4,%5,%6,%7}, {%8,%9}, {%0,%1,%2,%3};"
                        : "+f"(acc[mi][ni][0]), "+f"(acc[mi][ni][1]),
                          "+f"(acc[mi][ni][2]), "+f"(acc[mi][ni][3])
                        : "r"(a[mi][0]), "r"(a[mi][1]), "r"(a[mi][2]), "r"(a[mi][3]),
                          "r"(b[ni][0]), "r"(b[ni][1]));
        }
        if (c + 2 < c1) fill(c + 2, (c + 2 - c0) % MST);
        else cp_commit();
    }

    int r0 = bm + wm * 64 + (lane >> 2);
    int col0 = bn + wn * 32 + 2 * (lane & 3);
#pragma unroll
    for (int mi = 0; mi < 4; mi++)
#pragma unroll
        for (int ni = 0; ni < 4; ni++) {
            int cc = col0 + ni * 8;
            float v0 = acc[mi][ni][0], v1 = acc[mi][ni][1];
            float v2 = acc[mi][ni][2], v3 = acc[mi][ni][3];
            if (epi == 1) {
                float b0 = bias[cc], b1 = bias[cc + 1];
                v0 += b0; v1 += b1; v2 += b0; v3 += b1;
                v0 = (v0 > 20.f) ? v0 : log1pf(__expf(v0));
                v1 = (v1 > 20.f) ? v1 : log1pf(__expf(v1));
                v2 = (v2 > 20.f) ? v2 : log1pf(__expf(v2));
                v3 = (v3 > 20.f) ? v3 : log1pf(__expf(v3));
            }
            if (Ch) {
                *(__half2*)(Ch + (size_t)(r0 + mi * 16) * ldc + cc) =
                    __floats2half2_rn(v0, v1);
                *(__half2*)(Ch + (size_t)(r0 + mi * 16 + 8) * ldc + cc) =
                    __floats2half2_rn(v2, v3);
            } else {
                float* p0 = C + (size_t)(r0 + mi * 16) * ldc + cc;
                float* p1 = p0 + 8 * ldc;
                *(float2*)p0 = make_float2(v0, v1);
                *(float2*)p1 = make_float2(v2, v3);
            }
        }
}

// ---------------- reduce x_proj partials; emit xdbl fp32 + dt fp16 ----------
__global__ void reduce8x_kernel(const float* __restrict__ part,
                                float* __restrict__ xdbl,
                                __half* __restrict__ dt16) {
    int i = blockIdx.x * blockDim.x + threadIdx.x;
    if (i >= TQ * 128) return;
    int t = i >> 7, c = i & 127;
    float s = 0.f;
#pragma unroll
    for (int p = 0; p < 8; p++) s += part[(size_t)p * TQ * 128 + i];
    if (c < 96) xdbl[t * 96 + c] = s;
    dt16[i] = __float2half((c < DTRQ) ? s : 0.f);
}

// ---------------- causal depthwise conv (DC=4) + silu -> fp16 ---------------
__global__ void conv_silu_kernel(const __half* __restrict__ xz,
                                 const float* __restrict__ cw,
                                 const float* __restrict__ cb,
                                 __half* __restrict__ xc16) {
    int idx = blockIdx.x * blockDim.x + threadIdx.x;
    if (idx >= TQ * DIQ) return;
    int d = idx % DIQ;
    int t = idx / DIQ;
    int b = t / LQ;
    int l = t % LQ;
    float acc = cb[d];
#pragma unroll
    for (int k = 0; k < DCQ; k++) {
        int ll = l + k - (DCQ - 1);
        if (ll >= 0)
            acc = fmaf(cw[d * DCQ + k],
                       __half2float(xz[(size_t)(b * LQ + ll) * (2 * DIQ) + d]), acc);
    }
    float sig = 1.f / (1.f + __expf(-acc));
    xc16[idx] = __float2half(acc * sig);
}

// ================== chunked parallel scan =================================
// lane layout per warp: 2 channels (lane>>4), 16 states (lane&15).
#define SLC 64

// ---- pass 1: segment-local scan from 0 -> q[d,n]; also sum(delta) ----------
__global__ __launch_bounds__(256, 4)
void scan_p1_kernel(const __half* __restrict__ delta, const __half* __restrict__ u,
                    const float* __restrict__ xdbl, const float* __restrict__ A_log,
                    float* __restrict__ qseg, float* __restrict__ dsum) {
    __shared__ __half s_d[2][SLC * 16];
    __shared__ __half s_u[2][SLC * 16];
    __shared__ float s_B[2][SLC * 16];

    int d0 = blockIdx.x * 16;
    int seg = blockIdx.y;
    int b = blockIdx.z;
    int tid = threadIdx.x;
    int warp = tid >> 5;
    int lane = tid & 31;
    int chl = warp * 2 + (lane >> 4);
    int d = d0 + chl;
    int n = lane & 15;

    float Aval = -__expf(A_log[d * DSQ + n]);
    float hst = 0.f;
    float ds = 0.f;

    const int NCC = LSEG / SLC;   // 4
    int lbase = seg * LSEG;

    auto load_chunk = [&](int c, int buf) {
        int l0 = lbase + c * SLC;
#pragma unroll
        for (int e = tid; e < SLC * 16; e += 256) {
            int l = e >> 4, ch = e & 15;
            size_t t = (size_t)(b * LQ + l0 + l);
            cp_async4(&s_B[buf][e], xdbl + t * 96 + DTRQ + ch);
        }
#pragma unroll
        for (int e2 = tid; e2 < SLC * 8; e2 += 256) {
            int l = e2 >> 3, cp2 = e2 & 7;
            size_t t = (size_t)(b * LQ + l0 + l);
            cp_async4(&s_d[buf][l * 16 + cp2 * 2], delta + t * DIQ + d0 + cp2 * 2);
            cp_async4(&s_u[buf][l * 16 + cp2 * 2], u + t * DIQ + d0 + cp2 * 2);
        }
        cp_commit();
    };

    load_chunk(0, 0);
    for (int c = 0; c < NCC; c++) {
        int buf = c & 1;
        if (c + 1 < NCC) load_chunk(c + 1, (c + 1) & 1);
        else cp_commit();
        cp_wait1();
        __syncthreads();
#pragma unroll 8
        for (int l = 0; l < SLC; l++) {
            float dl = __half2float(s_d[buf][l * 16 + chl]);
            float uu = __half2float(s_u[buf][l * 16 + chl]);
            float Bv = s_B[buf][l * 16 + n];
            float a = __expf(dl * Aval);
            hst = fmaf(a, hst, dl * uu * Bv);
            ds += dl;
        }
        __syncthreads();
    }
    size_t base = ((size_t)(b * NSEG + seg) * DIQ + d);
    qseg[base * DSQ + n] = hst;
    if (n == 0) dsum[base] = ds;
}

// ---- pass 3: per-block prefix from qseg/dsum, then segment scan, emit y ----
__global__ __launch_bounds__(256, 2)
void scan_p3_kernel(const __half* __restrict__ delta, const __half* __restrict__ u,
                    const float* __restrict__ xdbl, const __half* __restrict__ xz,
                    const float* __restrict__ A_log, const float* __restrict__ Dskip,
                    const float* __restrict__ qseg, const float* __restrict__ dsum,
                    __half* __restrict__ a16) {
    __shared__ __half s_d[2][SLC * 16];
    __shared__ __half s_u[2][SLC * 16];
    __shared__ __half s_z[2][SLC * 16];
    __shared__ float s_B[2][SLC * 16];
    __shared__ float s_C[2][SLC * 16];
    __shared__ float s_y[SLC * 16];

    int d0 = blockIdx.x * 16;
    int seg = blockIdx.y;
    int b = blockIdx.z;
    int tid = threadIdx.x;
    int warp = tid >> 5;
    int lane = tid & 31;
    int chl = warp * 2 + (lane >> 4);
    int d = d0 + chl;
    int n = lane & 15;

    float Aval = -__expf(A_log[d * DSQ + n]);
    float Dval = Dskip[d];

    // in-register prefix over earlier segments (combine fused in)
    float hst = 0.f;
    for (int s = 0; s < seg; s++) {
        size_t base = ((size_t)(b * NSEG + s) * DIQ + d);
        hst = __expf(Aval * dsum[base]) * hst + qseg[base * DSQ + n];
    }

    const int NCC = LSEG / SLC;
    int lbase = seg * LSEG;

    auto load_chunk = [&](int c, int buf) {
        int l0 = lbase + c * SLC;
#pragma unroll
        for (int e = tid; e < SLC * 16; e += 256) {
            int l = e >> 4, ch = e & 15;
            size_t t = (size_t)(b * LQ + l0 + l);
            cp_async4(&s_B[buf][e], xdbl + t * 96 + DTRQ + ch);
            cp_async4(&s_C[buf][e], xdbl + t * 96 + DTRQ + DSQ + ch);
        }
#pragma unroll
        for (int e2 = tid; e2 < SLC * 8; e2 += 256) {
            int l = e2 >> 3, cp2 = e2 & 7;
            size_t t = (size_t)(b * LQ + l0 + l);
            cp_async4(&s_d[buf][l * 16 + cp2 * 2], delta + t * DIQ + d0 + cp2 * 2);
            cp_async4(&s_u[buf][l * 16 + cp2 * 2], u + t * DIQ + d0 + cp2 * 2);
            cp_async4(&s_z[buf][l * 16 + cp2 * 2],
                      xz + t * (2 * DIQ) + DIQ + d0 + cp2 * 2);
        }
        cp_commit();
    };

    load_chunk(0, 0);
    for (int c = 0; c < NCC; c++) {
        int buf = c & 1;
        if (c + 1 < NCC) load_chunk(c + 1, (c + 1) & 1);
        else cp_commit();
        cp_wait1();
        __syncthreads();
#pragma unroll 4
        for (int l = 0; l < SLC; l++) {
            float dl = __half2float(s_d[buf][l * 16 + chl]);
            float uu = __half2float(s_u[buf][l * 16 + chl]);
            float Bv = s_B[buf][l * 16 + n];
            float Cv = s_C[buf][l * 16 + n];
            float a = __expf(dl * Aval);
            hst = fmaf(a, hst, dl * uu * Bv);
            float p = hst * Cv;
            p += __shfl_xor_sync(0xffffffffu, p, 8);
            p += __shfl_xor_sync(0xffffffffu, p, 4);
            p += __shfl_xor_sync(0xffffffffu, p, 2);
            p += __shfl_xor_sync(0xffffffffu, p, 1);
            if (n == 0) {
                float zz = __half2float(s_z[buf][l * 16 + chl]);
                float sig = 1.f / (1.f + __expf(-zz));
                s_y[l * 16 + chl] = (p + uu * Dval) * zz * sig;
            }
        }
        __syncthreads();
        int l0 = lbase + c * SLC;
#pragma unroll
        for (int e = tid; e < SLC * 16; e += 256) {
            int l = e >> 4, ch = e & 15;
            a16[(size_t)(b * LQ + l0 + l) * DIQ + d0 + ch] = __float2half(s_y[e]);
        }
        __syncthreads();
    }
}

// ---------------- residual add + rmsnorm (+ optional fp16 cast) -------------
__global__ void add_rmsnorm_kernel(const float* __restrict__ yo,
                                   const float* __restrict__ hin,
                                   const float* __restrict__ w,
                                   float* __restrict__ out,
                                   __half* __restrict__ a16) {
    int row = blockIdx.x;
    const float* yr = yo + (size_t)row * EQ;
    const float* hr = hin + (size_t)row * EQ;
    int tid = threadIdx.x;
    float v[4];
    float ss = 0.f;
#pragma unroll
    for (int i = 0; i < 4; i++) {
        int j = tid + 256 * i;
        v[i] = yr[j] + hr[j];
        ss = fmaf(v[i], v[i], ss);
    }
#pragma unroll
    for (int off = 16; off; off >>= 1) ss += __shfl_xor_sync(0xffffffffu, ss, off);
    __shared__ float sp[8];
    if ((tid & 31) == 0) sp[tid >> 5] = ss;
    __syncthreads();
    if (tid == 0) {
        float t = 0.f;
#pragma unroll
        for (int i = 0; i < 8; i++) t += sp[i];
        sp[0] = t;
    }
    __syncthreads();
    float scale = rsqrtf(sp[0] * (1.f / EQ) + 1e-6f);
#pragma unroll
    for (int i = 0; i < 4; i++) {
        int j = tid + 256 * i;
        float ov = v[i] * scale * w[j];
        out[(size_t)row * EQ + j] = ov;
        if (a16) a16[(size_t)row * EQ + j] = __float2half(ov);
    }
}

// ---------------- host launcher ---------------------------------------------
extern "C" void kernel_launch(void* const* d_in, const int* in_sizes, int n_in,
                              void* d_out, int out_size) {
    const float* x    = (const float*)d_in[0];
    const float* pos  = (const float*)d_in[1];
    const float* inw  = (const float*)d_in[2];
    const float* cw   = (const float*)d_in[3];
    const float* cb   = (const float*)d_in[4];
    const float* xw   = (const float*)d_in[5];
    const float* dtw  = (const float*)d_in[6];
    const float* dtb  = (const float*)d_in[7];
    const float* alog = (const float*)d_in[8];
    const float* dsk  = (const float*)d_in[9];
    const float* ow   = (const float*)d_in[10];
    const float* nw   = (const float*)d_in[11];
    float* out = (float*)d_out;

    float *ph, *pxdbl, *pxpart, *pout, *pq, *pds;
    __half *pxz16, *pxc16, *pdt16, *pdelta16, *pa16;
    __half *pw16i, *pw16o, *pw16x, *pw16d;
    cudaGetSymbolAddress((void**)&ph, g_h);
    cudaGetSymbolAddress((void**)&pxz16, g_xz16);
    cudaGetSymbolAddress((void**)&pxc16, g_xc16);
    cudaGetSymbolAddress((void**)&pxdbl, g_xdbl);
    cudaGetSymbolAddress((void**)&pxpart, g_xpart);
    cudaGetSymbolAddress((void**)&pdt16, g_dt16);
    cudaGetSymbolAddress((void**)&pdelta16, g_delta16);
    cudaGetSymbolAddress((void**)&pout, g_out);
    cudaGetSymbolAddress((void**)&pq, g_qseg);
    cudaGetSymbolAddress((void**)&pds, g_dsum);
    cudaGetSymbolAddress((void**)&pa16, g_a16);
    cudaGetSymbolAddress((void**)&pw16i, g_w16i);
    cudaGetSymbolAddress((void**)&pw16o, g_w16o);
    cudaGetSymbolAddress((void**)&pw16x, g_w16x);
    cudaGetSymbolAddress((void**)&pw16d, g_w16d);

    const int SMB = MST * STB;   // 98304
    cudaFuncSetAttribute(mma_gemm_kernel,
                         cudaFuncAttributeMaxDynamicSharedMemorySize, SMB);

    // all-layer weight prep (single launch, off the per-layer critical path)
    prep_all_kernel<<<(NLQ * NPER + 255) / 256, 256>>>(
        inw, ow, xw, dtw, pw16i, pw16o, pw16x, pw16d);

    // h = x + pos, and fp16 cast for layer-0 in_proj
    embed_kernel<<<(TQ * EQ + 255) / 256, 256>>>(x, pos, ph, pa16);

    for (int layer = 0; layer < NLQ; layer++) {
        const float* cw_l  = cw  + (size_t)layer * DIQ * DCQ;
        const float* cb_l  = cb  + (size_t)layer * DIQ;
        const float* dtb_l = dtb + (size_t)layer * DIQ;
        const float* al_l  = alog + (size_t)layer * DIQ * DSQ;
        const float* ds_l  = dsk + (size_t)layer * DIQ;
        const float* nw_l  = nw  + (size_t)layer * EQ;
        const __half* w16i_l = pw16i + (size_t)layer * NI;
        const __half* w16o_l = pw16o + (size_t)layer * NO;
        const __half* w16x_l = pw16x + (size_t)layer * NX;
        const __half* w16d_l = pw16d + (size_t)layer * ND;

        // in_proj: xz = h @ in_w^T  (fp16, K=1024, fp16 output)
        mma_gemm_kernel<<<dim3(2 * DIQ / 128, TQ / 128, 1), 256, SMB>>>(
            pa16, w16i_l, nullptr, pxz16, EQ, 2 * DIQ, nullptr, 0);

        // xc = silu(causal_conv(xz[:, :DI]) + cb)  (fp16 only)
        conv_silu_kernel<<<(TQ * DIQ + 255) / 256, 256>>>(pxz16, cw_l, cb_l, pxc16);

        // x_proj: x_dbl = xc @ xw^T  (fp16, pad N 96->128, split-K=8)
        mma_gemm_kernel<<<dim3(1, TQ / 128, 8), 256, SMB>>>(
            pxc16, w16x_l, pxpart, nullptr, DIQ, 128, nullptr, 0);
        reduce8x_kernel<<<(TQ * 128 + 255) / 256, 256>>>(pxpart, pxdbl, pdt16);

        // dt_proj: delta = softplus(dt @ dtw^T + dtb)  (fp16, K pad 128)
        mma_gemm_kernel<<<dim3(DIQ / 128, TQ / 128, 1), 256, SMB>>>(
            pdt16, w16d_l, nullptr, pdelta16, 128, DIQ, dtb_l, 1);

        // chunked selective scan: pass1 -> pass3 (p3 does its own prefix)
        scan_p1_kernel<<<dim3(DIQ / 16, NSEG, BQ), 256>>>(
            pdelta16, pxc16, pxdbl, al_l, pq, pds);
        scan_p3_kernel<<<dim3(DIQ / 16, NSEG, BQ), 256>>>(
            pdelta16, pxc16, pxdbl, pxz16, al_l, ds_l, pq, pds, pa16);

        // out_proj: out = y @ ow^T  (fp16, K = 2048, fp32 output)
        mma_gemm_kernel<<<dim3(EQ / 128, TQ / 128, 1), 256, SMB>>>(
            pa16, w16o_l, pout, nullptr, DIQ, EQ, nullptr, 0);

        // h = rmsnorm(out + h) * norm_w  (+ fp16 cast for next layer's in_proj)
        float* dst = (layer == NLQ - 1) ? out : ph;
        __half* nxt = (layer == NLQ - 1) ? (__half*)nullptr : pa16;
        add_rmsnorm_kernel<<<TQ, 256>>>(pout, ph, nw_l, dst, nxt);
    }
}